// round 3
// baseline (speedup 1.0000x reference)
#include <cuda_runtime.h>
#include <cstdint>
#include <cstdio>

// PoolingRetriever collapses analytically:
//   softmax over a singleton axis == 1.0, so xi == 1 through all 5 steps,
//   out == v, and the whole module is:  out = (x @ Wv.T + bv) @ Wo.T + bo
// Two-stage fused GEMM through the 64-wide bottleneck (12.9 GFLOP total),
// tf32 tensor cores (mma.sync.m16n8k8), memory-bound target ~50-60us.

#define DIM      768
#define HH       64
#define TILE_M   128
#define KC       64
#define NTHREADS 256
#define XS_STRIDE 68                       // 68 % 32 == 4 -> conflict-free frags
#define SMEM_X_WORDS (TILE_M * XS_STRIDE)  // 8704
#define SMEM_W_WORDS (HH * XS_STRIDE)      // 4352
#define SMEM_BYTES   ((SMEM_X_WORDS + SMEM_W_WORDS + 64) * 4)  // 52480

__device__ __forceinline__ uint32_t f2tf32(float f) {
    uint32_t r;
    asm("cvt.rna.tf32.f32 %0, %1;" : "=r"(r) : "f"(f));
    return r;
}

__device__ __forceinline__ void mma8(float d[4], const uint32_t a[4], const uint32_t b[2]) {
    asm volatile(
        "mma.sync.aligned.m16n8k8.row.col.f32.tf32.tf32.f32 "
        "{%0,%1,%2,%3}, {%4,%5,%6,%7}, {%8,%9}, {%0,%1,%2,%3};\n"
        : "+f"(d[0]), "+f"(d[1]), "+f"(d[2]), "+f"(d[3])
        : "r"(a[0]), "r"(a[1]), "r"(a[2]), "r"(a[3]), "r"(b[0]), "r"(b[1]));
}

__global__ __launch_bounds__(NTHREADS, 2)
void pooling_retriever_kernel(const float* __restrict__ x,
                              const float* __restrict__ Wv,
                              const float* __restrict__ bv,
                              const float* __restrict__ Wo,
                              const float* __restrict__ bo,
                              float* __restrict__ out) {
    extern __shared__ uint32_t smem[];
    uint32_t* Xs = smem;                                 // 128 x 68 tf32; reused for T
    uint32_t* Ws = smem + SMEM_X_WORDS;                  // 64 x 68 tf32 (Wv then Wo chunks)
    float* bias_s = (float*)(smem + SMEM_X_WORDS + SMEM_W_WORDS);  // 64 floats

    const int tid  = threadIdx.x;
    const int warp = tid >> 5;
    const int lane = tid & 31;
    const int gid  = lane >> 2;   // groupID 0..7
    const int t4   = lane & 3;    // thread-in-group 0..3
    const int m0   = blockIdx.x * TILE_M;
    const int wrow = warp * 16;   // warp's 16-row strip within tile

    if (tid < HH) bias_s[tid] = bv[tid];

    // ---------------- Stage 1: T = x @ Wv.T + bv  (128 x 64) ----------------
    float acc[8][4];
    #pragma unroll
    for (int nb = 0; nb < 8; nb++)
        #pragma unroll
        for (int i = 0; i < 4; i++) acc[nb][i] = 0.f;

    for (int kc = 0; kc < DIM; kc += KC) {
        __syncthreads();
        // x chunk: 128 x 64 -> Xs (tf32)
        #pragma unroll
        for (int i = 0; i < (TILE_M * KC / 4) / NTHREADS; i++) {   // 8 iters
            int idx = tid + i * NTHREADS;
            int r  = idx >> 4;
            int c4 = (idx & 15) << 2;
            float4 v = *(const float4*)(x + (size_t)(m0 + r) * DIM + kc + c4);
            uint32_t* d = Xs + r * XS_STRIDE + c4;
            d[0] = f2tf32(v.x); d[1] = f2tf32(v.y); d[2] = f2tf32(v.z); d[3] = f2tf32(v.w);
        }
        // Wv chunk: 64 x 64 -> Ws (tf32)  (Wv is [n][k] row-major == col-major B)
        #pragma unroll
        for (int i = 0; i < (HH * KC / 4) / NTHREADS; i++) {       // 4 iters
            int idx = tid + i * NTHREADS;
            int r  = idx >> 4;
            int c4 = (idx & 15) << 2;
            float4 v = *(const float4*)(Wv + (size_t)r * DIM + kc + c4);
            uint32_t* d = Ws + r * XS_STRIDE + c4;
            d[0] = f2tf32(v.x); d[1] = f2tf32(v.y); d[2] = f2tf32(v.z); d[3] = f2tf32(v.w);
        }
        __syncthreads();
        #pragma unroll
        for (int ks = 0; ks < KC / 8; ks++) {
            uint32_t a[4];
            const uint32_t* r0p = Xs + (wrow + gid)     * XS_STRIDE + ks * 8;
            const uint32_t* r1p = Xs + (wrow + gid + 8) * XS_STRIDE + ks * 8;
            a[0] = r0p[t4]; a[1] = r1p[t4]; a[2] = r0p[t4 + 4]; a[3] = r1p[t4 + 4];
            #pragma unroll
            for (int nb = 0; nb < 8; nb++) {
                uint32_t b[2];
                const uint32_t* bp = Ws + (nb * 8 + gid) * XS_STRIDE + ks * 8;
                b[0] = bp[t4]; b[1] = bp[t4 + 4];
                mma8(acc[nb], a, b);
            }
        }
    }
    __syncthreads();   // all warps done reading Xs before overwriting with T

    // Write T = acc + bv into Xs as tf32 (each warp writes only its own 16 rows)
    #pragma unroll
    for (int nb = 0; nb < 8; nb++) {
        int c = nb * 8 + 2 * t4;
        float b0 = bias_s[c], b1 = bias_s[c + 1];
        uint32_t* d0 = Xs + (wrow + gid)     * XS_STRIDE + c;
        uint32_t* d1 = Xs + (wrow + gid + 8) * XS_STRIDE + c;
        d0[0] = f2tf32(acc[nb][0] + b0);
        d0[1] = f2tf32(acc[nb][1] + b1);
        d1[0] = f2tf32(acc[nb][2] + b0);
        d1[1] = f2tf32(acc[nb][3] + b1);
    }
    __syncwarp();      // cross-lane T reads below stay within the warp's rows

    // Persistent A fragments of T for stage 2
    uint32_t ta[8][4];
    #pragma unroll
    for (int ks = 0; ks < 8; ks++) {
        const uint32_t* r0p = Xs + (wrow + gid)     * XS_STRIDE + ks * 8;
        const uint32_t* r1p = Xs + (wrow + gid + 8) * XS_STRIDE + ks * 8;
        ta[ks][0] = r0p[t4]; ta[ks][1] = r1p[t4];
        ta[ks][2] = r0p[t4 + 4]; ta[ks][3] = r1p[t4 + 4];
    }

    // ---------------- Stage 2: out = T @ Wo.T + bo  (128 x 768) ----------------
    for (int nc = 0; nc < DIM; nc += 64) {
        __syncthreads();
        // Wo chunk: rows nc..nc+63, 64 cols -> Ws (Wo is [n][k] row-major == col-major B)
        #pragma unroll
        for (int i = 0; i < (64 * HH / 4) / NTHREADS; i++) {   // 4 iters
            int idx = tid + i * NTHREADS;
            int r  = idx >> 4;
            int c4 = (idx & 15) << 2;
            float4 v = *(const float4*)(Wo + (size_t)(nc + r) * HH + c4);
            uint32_t* d = Ws + r * XS_STRIDE + c4;
            d[0] = f2tf32(v.x); d[1] = f2tf32(v.y); d[2] = f2tf32(v.z); d[3] = f2tf32(v.w);
        }
        if (tid < 64) bias_s[tid] = bo[nc + tid];
        __syncthreads();

        float oacc[8][4];
        #pragma unroll
        for (int nb = 0; nb < 8; nb++)
            #pragma unroll
            for (int i = 0; i < 4; i++) oacc[nb][i] = 0.f;

        #pragma unroll
        for (int ks = 0; ks < 8; ks++) {
            #pragma unroll
            for (int nb = 0; nb < 8; nb++) {
                uint32_t b[2];
                const uint32_t* bp = Ws + (nb * 8 + gid) * XS_STRIDE + ks * 8;
                b[0] = bp[t4]; b[1] = bp[t4 + 4];
                mma8(oacc[nb], ta[ks], b);
            }
        }
        // Epilogue: += bo, store float2 pairs
        #pragma unroll
        for (int nb = 0; nb < 8; nb++) {
            int c = nb * 8 + 2 * t4;
            float b0 = bias_s[c], b1 = bias_s[c + 1];
            float2 v0 = make_float2(oacc[nb][0] + b0, oacc[nb][1] + b1);
            float2 v1 = make_float2(oacc[nb][2] + b0, oacc[nb][3] + b1);
            *(float2*)(out + (size_t)(m0 + wrow + gid)     * DIM + nc + c) = v0;
            *(float2*)(out + (size_t)(m0 + wrow + gid + 8) * DIM + nc + c) = v1;
        }
    }
}

extern "C" void kernel_launch(void* const* d_in, const int* in_sizes, int n_in,
                              void* d_out, int out_size) {
    // metadata order: x, q_state, Wq, bq, Wk, bk, Wv, bv, Wo, bo
    const float* x  = (const float*)d_in[0];
    const float* Wv = (const float*)d_in[6];
    const float* bv = (const float*)d_in[7];
    const float* Wo = (const float*)d_in[8];
    const float* bo = (const float*)d_in[9];
    float* out = (float*)d_out;

    const int n_rows = in_sizes[0] / DIM;      // 65536
    const int grid   = n_rows / TILE_M;        // 512

    cudaFuncSetAttribute(pooling_retriever_kernel,
                         cudaFuncAttributeMaxDynamicSharedMemorySize, SMEM_BYTES);
    pooling_retriever_kernel<<<grid, NTHREADS, SMEM_BYTES>>>(x, Wv, bv, Wo, bo, out);
}